// round 1
// baseline (speedup 1.0000x reference)
#include <cuda_runtime.h>

// ---------------------------------------------------------------------------
// ImprovedGeometricTrunk: fused geometry-features + 3-layer MLP (fp32 baseline)
//   rows M = B*N = 524288
//   feats[13] -> W1[13,128]+LN+ReLU -> W2[128,128]+LN+ReLU -> W3[128,64]
// One block = 128 rows, 256 threads. All weights + activations in shared.
// ---------------------------------------------------------------------------

#define PI_F 3.14159265358979323846f

constexpr int Hh        = 128;
constexpr int Ff        = 13;
constexpr int Pp        = 64;
constexpr int TILE      = 128;
constexpr int NTHREADS  = 256;
constexpr int SA_STRIDE = 132;   // 128 + 4 pad: column-k reads hit distinct banks
constexpr int SF_STRIDE = 17;    // odd stride: per-row feat reads spread banks

constexpr int OFF_W2  = 0;
constexpr int OFF_W3  = OFF_W2  + Hh * Hh;        // 16384
constexpr int OFF_W1  = OFF_W3  + Hh * Pp;        // +8192
constexpr int OFF_B1  = OFF_W1  + Ff * Hh;        // +1664
constexpr int OFF_G1  = OFF_B1  + Hh;
constexpr int OFF_BT1 = OFF_G1  + Hh;
constexpr int OFF_B2  = OFF_BT1 + Hh;
constexpr int OFF_G2  = OFF_B2  + Hh;
constexpr int OFF_BT2 = OFF_G2  + Hh;
constexpr int OFF_B3  = OFF_BT2 + Hh;             // 64 entries
constexpr int OFF_A   = OFF_B3  + Pp;             // 128*132 activations
constexpr int OFF_Fe  = OFF_A   + TILE * SA_STRIDE;
constexpr int SMEM_FLOATS = OFF_Fe + TILE * SF_STRIDE;
// ~46144 floats = ~180.3 KB dynamic shared

__device__ __forceinline__ void ln_relu_inplace(float* sm, int tid,
                                                const float* g, const float* bt) {
    const int warp = tid >> 5;
    const int lane = tid & 31;
    for (int r = warp; r < TILE; r += NTHREADS / 32) {
        float* rowp = &sm[OFF_A + r * SA_STRIDE];
        float x0 = rowp[lane];
        float x1 = rowp[lane + 32];
        float x2 = rowp[lane + 64];
        float x3 = rowp[lane + 96];
        float s = x0 + x1 + x2 + x3;
        #pragma unroll
        for (int o = 16; o > 0; o >>= 1) s += __shfl_xor_sync(0xffffffffu, s, o);
        const float mu = s * (1.0f / 128.0f);
        const float d0 = x0 - mu, d1 = x1 - mu, d2 = x2 - mu, d3 = x3 - mu;
        float v = d0 * d0 + d1 * d1 + d2 * d2 + d3 * d3;
        #pragma unroll
        for (int o = 16; o > 0; o >>= 1) v += __shfl_xor_sync(0xffffffffu, v, o);
        const float inv = rsqrtf(v * (1.0f / 128.0f) + 1e-5f);
        rowp[lane]      = fmaxf(d0 * inv * g[lane]      + bt[lane],      0.0f);
        rowp[lane + 32] = fmaxf(d1 * inv * g[lane + 32] + bt[lane + 32], 0.0f);
        rowp[lane + 64] = fmaxf(d2 * inv * g[lane + 64] + bt[lane + 64], 0.0f);
        rowp[lane + 96] = fmaxf(d3 * inv * g[lane + 96] + bt[lane + 96], 0.0f);
    }
}

__global__ __launch_bounds__(NTHREADS, 1)
void geo_trunk_kernel(const float* __restrict__ coords,
                      const float* __restrict__ ref_theta,
                      const float* __restrict__ ref_phi,
                      const float* __restrict__ W1, const float* __restrict__ b1,
                      const float* __restrict__ g1, const float* __restrict__ bt1,
                      const float* __restrict__ W2, const float* __restrict__ b2,
                      const float* __restrict__ g2, const float* __restrict__ bt2,
                      const float* __restrict__ W3, const float* __restrict__ b3,
                      float* __restrict__ out, int M) {
    extern __shared__ float sm[];
    const int tid = threadIdx.x;

    // ---- Phase 0: stage all weights into shared ----
    for (int i = tid; i < Hh * Hh; i += NTHREADS) sm[OFF_W2 + i] = W2[i];
    for (int i = tid; i < Hh * Pp; i += NTHREADS) sm[OFF_W3 + i] = W3[i];
    for (int i = tid; i < Ff * Hh; i += NTHREADS) sm[OFF_W1 + i] = W1[i];
    if (tid < Hh) {
        sm[OFF_B1  + tid] = b1[tid];
        sm[OFF_G1  + tid] = g1[tid];
        sm[OFF_BT1 + tid] = bt1[tid];
        sm[OFF_B2  + tid] = b2[tid];
        sm[OFF_G2  + tid] = g2[tid];
        sm[OFF_BT2 + tid] = bt2[tid];
    }
    if (tid < Pp) sm[OFF_B3 + tid] = b3[tid];

    // ---- Phase 1: geometry features (threads 0..127, one row each) ----
    if (tid < TILE) {
        const int row = blockIdx.x * TILE + tid;
        float theta = 0.0f, phi = 0.0f;
        if (row < M) {
            theta = coords[2 * row];
            phi   = coords[2 * row + 1];
        }
        float st, ct;
        sincosf(theta, &st, &ct);
        float* f = &sm[OFF_Fe + tid * SF_STRIDE];
        #pragma unroll
        for (int k = 0; k < 10; ++k) {
            const float rt = ref_theta[k];
            const float rp = ref_phi[k];
            float srt, crt;
            sincosf(rt, &srt, &crt);
            float cd = ct * crt + st * srt * cosf(phi - rp);
            cd = fminf(1.0f, fmaxf(-1.0f, cd));
            f[k] = acosf(cd) * (1.0f / PI_F);
        }
        f[10] = theta * (1.0f / PI_F);
        f[11] = phi * (1.0f / (2.0f * PI_F));
        f[12] = 1.0f;
    }
    __syncthreads();

    // ---- Phase 2: L1 = feats[128,13] @ W1[13,128] + b1 -> sA ----
    {
        const int r  = tid >> 1;
        const int c0 = (tid & 1) * 64;
        float4 acc[16];
        #pragma unroll
        for (int j = 0; j < 16; ++j)
            acc[j] = *(const float4*)&sm[OFF_B1 + c0 + 4 * j];
        const float* fr = &sm[OFF_Fe + r * SF_STRIDE];
        #pragma unroll
        for (int k = 0; k < Ff; ++k) {
            const float fv = fr[k];
            const float4* w = (const float4*)&sm[OFF_W1 + k * Hh + c0];
            #pragma unroll
            for (int j = 0; j < 16; ++j) {
                float4 wv = w[j];
                acc[j].x = fmaf(fv, wv.x, acc[j].x);
                acc[j].y = fmaf(fv, wv.y, acc[j].y);
                acc[j].z = fmaf(fv, wv.z, acc[j].z);
                acc[j].w = fmaf(fv, wv.w, acc[j].w);
            }
        }
        float4* dst = (float4*)&sm[OFF_A + r * SA_STRIDE + c0];
        #pragma unroll
        for (int j = 0; j < 16; ++j) dst[j] = acc[j];
    }
    __syncthreads();

    // ---- Phase 3: LN1 + ReLU ----
    ln_relu_inplace(sm, tid, &sm[OFF_G1], &sm[OFF_BT1]);
    __syncthreads();

    // ---- Phase 4: L2 = h1[128,128] @ W2[128,128] + b2 (8x8 register tiles) ----
    {
        const int ty = tid >> 4, tx = tid & 15;
        const int r0 = ty * 8, c0 = tx * 8;
        float acc[8][8];
        #pragma unroll
        for (int i = 0; i < 8; ++i)
            #pragma unroll
            for (int j = 0; j < 8; ++j) acc[i][j] = 0.0f;

        const float* A = &sm[OFF_A];
        const float* B = &sm[OFF_W2];
        #pragma unroll 8
        for (int k = 0; k < Hh; ++k) {
            float a[8];
            #pragma unroll
            for (int i = 0; i < 8; ++i) a[i] = A[(r0 + i) * SA_STRIDE + k];
            const float4 bv0 = *(const float4*)&B[k * Hh + c0];
            const float4 bv1 = *(const float4*)&B[k * Hh + c0 + 4];
            const float bb[8] = {bv0.x, bv0.y, bv0.z, bv0.w, bv1.x, bv1.y, bv1.z, bv1.w};
            #pragma unroll
            for (int i = 0; i < 8; ++i)
                #pragma unroll
                for (int j = 0; j < 8; ++j)
                    acc[i][j] = fmaf(a[i], bb[j], acc[i][j]);
        }
        __syncthreads();   // everyone done reading h1 before overwrite
        #pragma unroll
        for (int i = 0; i < 8; ++i)
            #pragma unroll
            for (int j = 0; j < 8; ++j)
                sm[OFF_A + (r0 + i) * SA_STRIDE + c0 + j] = acc[i][j] + sm[OFF_B2 + c0 + j];
    }
    __syncthreads();

    // ---- Phase 5: LN2 + ReLU ----
    ln_relu_inplace(sm, tid, &sm[OFF_G2], &sm[OFF_BT2]);
    __syncthreads();

    // ---- Phase 6: out = h2[128,128] @ W3[128,64] + b3 -> global ----
    {
        const int ty = tid >> 4, tx = tid & 15;
        const int r0 = ty * 8, c0 = tx * 4;
        float acc[8][4];
        #pragma unroll
        for (int i = 0; i < 8; ++i)
            #pragma unroll
            for (int j = 0; j < 4; ++j) acc[i][j] = 0.0f;

        const float* A = &sm[OFF_A];
        const float* B = &sm[OFF_W3];
        #pragma unroll 8
        for (int k = 0; k < Hh; ++k) {
            float a[8];
            #pragma unroll
            for (int i = 0; i < 8; ++i) a[i] = A[(r0 + i) * SA_STRIDE + k];
            const float4 bv = *(const float4*)&B[k * Pp + c0];
            #pragma unroll
            for (int i = 0; i < 8; ++i) {
                acc[i][0] = fmaf(a[i], bv.x, acc[i][0]);
                acc[i][1] = fmaf(a[i], bv.y, acc[i][1]);
                acc[i][2] = fmaf(a[i], bv.z, acc[i][2]);
                acc[i][3] = fmaf(a[i], bv.w, acc[i][3]);
            }
        }
        const float4 bias = *(const float4*)&sm[OFF_B3 + c0];
        #pragma unroll
        for (int i = 0; i < 8; ++i) {
            const int row = blockIdx.x * TILE + r0 + i;
            if (row < M) {
                float4 o;
                o.x = acc[i][0] + bias.x;
                o.y = acc[i][1] + bias.y;
                o.z = acc[i][2] + bias.z;
                o.w = acc[i][3] + bias.w;
                *(float4*)&out[row * Pp + c0] = o;
            }
        }
    }
}

extern "C" void kernel_launch(void* const* d_in, const int* in_sizes, int n_in,
                              void* d_out, int out_size) {
    const float* coords    = (const float*)d_in[0];
    const float* ref_theta = (const float*)d_in[1];
    const float* ref_phi   = (const float*)d_in[2];
    const float* W1  = (const float*)d_in[3];
    const float* b1  = (const float*)d_in[4];
    const float* g1  = (const float*)d_in[5];
    const float* bt1 = (const float*)d_in[6];
    const float* W2  = (const float*)d_in[7];
    const float* b2  = (const float*)d_in[8];
    const float* g2  = (const float*)d_in[9];
    const float* bt2 = (const float*)d_in[10];
    const float* W3  = (const float*)d_in[11];
    const float* b3  = (const float*)d_in[12];
    float* out = (float*)d_out;

    const int M = in_sizes[0] / 2;
    const int blocks = (M + TILE - 1) / TILE;
    const size_t smem = (size_t)SMEM_FLOATS * sizeof(float);

    cudaFuncSetAttribute(geo_trunk_kernel,
                         cudaFuncAttributeMaxDynamicSharedMemorySize, (int)smem);

    geo_trunk_kernel<<<blocks, NTHREADS, smem>>>(
        coords, ref_theta, ref_phi,
        W1, b1, g1, bt1, W2, b2, g2, bt2, W3, b3,
        out, M);
}

// round 3
// speedup vs baseline: 1.9956x; 1.9956x over previous
#include <cuda_runtime.h>
#include <cuda_bf16.h>
#include <cstdint>

#define PI_F 3.14159265358979323846f

// ---------------------------------------------------------------------------
// bf16 mma.sync (m16n8k16) split-precision fused trunk for sm_100 (no 'a').
//   Persistent: grid<=148, 256 threads (8 warps), 128-row tiles.
//   Weights in SMEM as Bs[n][k] bf16 hi/lo (k-contiguous, padded strides).
//   Activations in SMEM rows (132-word stride): fp32 D / bf16 hi|lo A halves.
//   D = Ahi*Bhi + Ahi*Blo + Alo*Bhi  (fp32 accum)  => ~1e-5 rel error.
// ---------------------------------------------------------------------------

constexpr int TILE = 128;
constexpr int NTH  = 256;
constexpr int NSM  = 148;

// 32-bit word offsets in dynamic shared
constexpr int SRT  = 0;     // 10 sin(ref_theta)
constexpr int CRT  = 16;    // 10 cos(ref_theta)
constexpr int RPHI = 32;    // 10 ref_phi
constexpr int B1o  = 48,  G1o = 176, BT1o = 304;
constexpr int B2o  = 432, G2o = 560, BT2o = 688;
constexpr int B3o  = 816;           // 64 floats
constexpr int W1H  = 896;           // 128n x 12w (k=16 bf16, padded)
constexpr int W1L  = 2432;
constexpr int W2H  = 3968;          // 128n x 68w (k=128 bf16)
constexpr int W2L  = 12672;
constexpr int W3H  = 21376;         // 64n x 68w
constexpr int W3L  = 25728;
constexpr int ACT  = 30080;         // 128 rows x 132w
constexpr int SMEM_WORDS = ACT + 128 * 132;   // 46976 words = 187904 B

__device__ __forceinline__ uint32_t pack2(float a, float b) {
    __nv_bfloat162 t = __floats2bfloat162_rn(a, b);   // a -> low half
    return *reinterpret_cast<uint32_t*>(&t);
}

__device__ __forceinline__ void mma16816(float* d, const uint32_t* a,
                                         uint32_t b0, uint32_t b1) {
    asm volatile(
        "mma.sync.aligned.m16n8k16.row.col.f32.bf16.bf16.f32 "
        "{%0,%1,%2,%3}, {%4,%5,%6,%7}, {%8,%9}, {%0,%1,%2,%3};\n"
        : "+f"(d[0]), "+f"(d[1]), "+f"(d[2]), "+f"(d[3])
        : "r"(a[0]), "r"(a[1]), "r"(a[2]), "r"(a[3]), "r"(b0), "r"(b1));
}

// LayerNorm(x + bias) * gamma + beta, ReLU, bf16 hi/lo split, in place.
// Warp w handles rows 16w..16w+15. Row layout before: 128 f32 (words 0..127).
// After: hi bf16x2 words [0,64), lo words [64,128).
__device__ __forceinline__ void ln_relu(uint32_t* sm, int w, int lane,
                                        int bo, int go, int to) {
    float* smf = reinterpret_cast<float*>(sm);
    const float2 bA = *(const float2*)&smf[bo + 2 * lane];
    const float2 bB = *(const float2*)&smf[bo + 64 + 2 * lane];
    const float2 gA = *(const float2*)&smf[go + 2 * lane];
    const float2 gB = *(const float2*)&smf[go + 64 + 2 * lane];
    const float2 tA = *(const float2*)&smf[to + 2 * lane];
    const float2 tB = *(const float2*)&smf[to + 64 + 2 * lane];
    for (int i = 0; i < 16; ++i) {
        const int rw = ACT + (w * 16 + i) * 132;
        float2 p0 = *(const float2*)&smf[rw + 2 * lane];        // cols 2l,2l+1
        float2 p1 = *(const float2*)&smf[rw + 64 + 2 * lane];   // cols 64+2l,..
        float x0 = p0.x + bA.x, x1 = p0.y + bA.y;
        float x2 = p1.x + bB.x, x3 = p1.y + bB.y;
        float s = x0 + x1 + x2 + x3;
        #pragma unroll
        for (int o = 16; o > 0; o >>= 1) s += __shfl_xor_sync(0xffffffffu, s, o);
        const float mu = s * (1.0f / 128.0f);
        const float d0 = x0 - mu, d1 = x1 - mu, d2 = x2 - mu, d3 = x3 - mu;
        float v = d0 * d0 + d1 * d1 + d2 * d2 + d3 * d3;
        #pragma unroll
        for (int o = 16; o > 0; o >>= 1) v += __shfl_xor_sync(0xffffffffu, v, o);
        const float inv = rsqrtf(v * (1.0f / 128.0f) + 1e-5f);
        float y0 = fmaxf(d0 * inv * gA.x + tA.x, 0.0f);
        float y1 = fmaxf(d1 * inv * gA.y + tA.y, 0.0f);
        float y2 = fmaxf(d2 * inv * gB.x + tB.x, 0.0f);
        float y3 = fmaxf(d3 * inv * gB.y + tB.y, 0.0f);
        float h0 = __bfloat162float(__float2bfloat16(y0));
        float h1 = __bfloat162float(__float2bfloat16(y1));
        float h2 = __bfloat162float(__float2bfloat16(y2));
        float h3 = __bfloat162float(__float2bfloat16(y3));
        sm[rw + lane]      = pack2(h0, h1);
        sm[rw + 32 + lane] = pack2(h2, h3);
        sm[rw + 64 + lane] = pack2(y0 - h0, y1 - h1);
        sm[rw + 96 + lane] = pack2(y2 - h2, y3 - h3);
    }
}

__global__ __launch_bounds__(NTH, 1)
void geo_trunk_mma(const float* __restrict__ coords,
                   const float* __restrict__ ref_theta,
                   const float* __restrict__ ref_phi,
                   const float* __restrict__ W1, const float* __restrict__ b1,
                   const float* __restrict__ g1, const float* __restrict__ bt1,
                   const float* __restrict__ W2, const float* __restrict__ b2,
                   const float* __restrict__ g2, const float* __restrict__ bt2,
                   const float* __restrict__ W3, const float* __restrict__ b3,
                   float* __restrict__ out, int M) {
    extern __shared__ uint32_t sm[];
    float* smf = reinterpret_cast<float*>(sm);
    uint16_t* smh = reinterpret_cast<uint16_t*>(sm);
    const int tid = threadIdx.x;
    const int w = tid >> 5, lane = tid & 31;
    const int g = lane >> 2, t = lane & 3;

    // ---- stage params + split weights ----
    for (int i = W1H + tid; i < W2H; i += NTH) sm[i] = 0;   // zero W1 (k pad)
    if (tid < 128) {
        smf[B1o + tid] = b1[tid];  smf[G1o + tid] = g1[tid];  smf[BT1o + tid] = bt1[tid];
        smf[B2o + tid] = b2[tid];  smf[G2o + tid] = g2[tid];  smf[BT2o + tid] = bt2[tid];
    }
    if (tid < 64) smf[B3o + tid] = b3[tid];
    if (tid < 10) {
        float s, c;
        sincosf(ref_theta[tid], &s, &c);
        smf[SRT + tid] = s; smf[CRT + tid] = c; smf[RPHI + tid] = ref_phi[tid];
    }
    __syncthreads();
    for (int i = tid; i < 13 * 128; i += NTH) {          // W1[f][h] -> Bs[h][f]
        int f = i >> 7, h = i & 127;
        float v = W1[i];
        __nv_bfloat16 hv = __float2bfloat16(v);
        __nv_bfloat16 lv = __float2bfloat16(v - __bfloat162float(hv));
        int base = (W1H + h * 12) * 2 + f;
        smh[base] = *reinterpret_cast<uint16_t*>(&hv);
        smh[base + (W1L - W1H) * 2] = *reinterpret_cast<uint16_t*>(&lv);
    }
    for (int i = tid; i < 128 * 128; i += NTH) {         // W2[k][n] -> Bs[n][k]
        int k = i >> 7, n = i & 127;
        float v = W2[i];
        __nv_bfloat16 hv = __float2bfloat16(v);
        __nv_bfloat16 lv = __float2bfloat16(v - __bfloat162float(hv));
        int base = (W2H + n * 68) * 2 + k;
        smh[base] = *reinterpret_cast<uint16_t*>(&hv);
        smh[base + (W2L - W2H) * 2] = *reinterpret_cast<uint16_t*>(&lv);
    }
    for (int i = tid; i < 128 * 64; i += NTH) {          // W3[k][p] -> Bs[p][k]
        int k = i >> 6, n = i & 63;
        float v = W3[i];
        __nv_bfloat16 hv = __float2bfloat16(v);
        __nv_bfloat16 lv = __float2bfloat16(v - __bfloat162float(hv));
        int base = (W3H + n * 68) * 2 + k;
        smh[base] = *reinterpret_cast<uint16_t*>(&hv);
        smh[base + (W3L - W3H) * 2] = *reinterpret_cast<uint16_t*>(&lv);
    }
    __syncthreads();

    const int ntiles = (M + TILE - 1) / TILE;
    for (int tile = blockIdx.x; tile < ntiles; tile += gridDim.x) {
        const int rbase = tile * TILE;

        // ---- features: thread = row (threads 0..127) ----
        if (tid < 128) {
            const int row = rbase + tid;
            float th = 0.0f, ph = 0.0f;
            if (row < M) {
                float2 cc = reinterpret_cast<const float2*>(coords)[row];
                th = cc.x; ph = cc.y;
            }
            float st, ct;
            sincosf(th, &st, &ct);
            float f[16];
            #pragma unroll
            for (int k = 0; k < 10; ++k) {
                float cd = ct * smf[CRT + k] + st * smf[SRT + k] * cosf(ph - smf[RPHI + k]);
                cd = fminf(1.0f, fmaxf(-1.0f, cd));
                f[k] = acosf(cd) * (1.0f / PI_F);
            }
            f[10] = th * (1.0f / PI_F);
            f[11] = ph * (1.0f / (2.0f * PI_F));
            f[12] = 1.0f; f[13] = 0.0f; f[14] = 0.0f; f[15] = 0.0f;
            const int rw = ACT + tid * 132;
            #pragma unroll
            for (int j = 0; j < 8; ++j) {
                float a = f[2 * j], b = f[2 * j + 1];
                float ha = __bfloat162float(__float2bfloat16(a));
                float hb = __bfloat162float(__float2bfloat16(b));
                sm[rw + j]      = pack2(ha, hb);
                sm[rw + 64 + j] = pack2(a - ha, b - hb);
            }
        }
        __syncthreads();

        // ---- L1: warp w -> rows 16w..16w+15, n=128, k=16 ----
        {
            uint32_t ah[4], al[4];
            const int ar = ACT + (16 * w + g) * 132 + t;
            ah[0] = sm[ar];            ah[2] = sm[ar + 4];
            ah[1] = sm[ar + 8 * 132];  ah[3] = sm[ar + 8 * 132 + 4];
            al[0] = sm[ar + 64];           al[2] = sm[ar + 68];
            al[1] = sm[ar + 8 * 132 + 64]; al[3] = sm[ar + 8 * 132 + 68];
            float acc[16][4];
            #pragma unroll
            for (int nt = 0; nt < 16; ++nt)
                #pragma unroll
                for (int j = 0; j < 4; ++j) acc[nt][j] = 0.0f;
            #pragma unroll
            for (int nt = 0; nt < 16; ++nt) {
                const int bw = W1H + (8 * nt + g) * 12 + t;
                uint32_t bh0 = sm[bw], bh1 = sm[bw + 4];
                uint32_t bl0 = sm[bw + (W1L - W1H)], bl1 = sm[bw + (W1L - W1H) + 4];
                mma16816(acc[nt], ah, bh0, bh1);
                mma16816(acc[nt], ah, bl0, bl1);
                mma16816(acc[nt], al, bh0, bh1);
            }
            // own-strip store: no cross-warp hazard
            #pragma unroll
            for (int nt = 0; nt < 16; ++nt) {
                const int col = 8 * nt + 2 * t;
                const int r0 = ACT + (16 * w + g) * 132 + col;
                *(float2*)&smf[r0]           = make_float2(acc[nt][0], acc[nt][1]);
                *(float2*)&smf[r0 + 8 * 132] = make_float2(acc[nt][2], acc[nt][3]);
            }
        }
        __syncthreads();
        ln_relu(sm, w, lane, B1o, G1o, BT1o);
        __syncthreads();

        // ---- L2: warp block m32 x n64, k=128 ----
        {
            const int m0 = (w & 3) * 32, n0 = (w >> 2) * 64;
            float acc[2][8][4];
            #pragma unroll
            for (int mt = 0; mt < 2; ++mt)
                #pragma unroll
                for (int nt = 0; nt < 8; ++nt)
                    #pragma unroll
                    for (int j = 0; j < 4; ++j) acc[mt][nt][j] = 0.0f;
            #pragma unroll
            for (int ks = 0; ks < 8; ++ks) {
                uint32_t ah[2][4], al[2][4];
                #pragma unroll
                for (int mt = 0; mt < 2; ++mt) {
                    const int ar = ACT + (m0 + 16 * mt + g) * 132 + 8 * ks + t;
                    ah[mt][0] = sm[ar];            ah[mt][2] = sm[ar + 4];
                    ah[mt][1] = sm[ar + 8 * 132];  ah[mt][3] = sm[ar + 8 * 132 + 4];
                    al[mt][0] = sm[ar + 64];           al[mt][2] = sm[ar + 68];
                    al[mt][1] = sm[ar + 8 * 132 + 64]; al[mt][3] = sm[ar + 8 * 132 + 68];
                }
                #pragma unroll
                for (int nt = 0; nt < 8; ++nt) {
                    const int bw = W2H + (n0 + 8 * nt + g) * 68 + 8 * ks + t;
                    uint32_t bh0 = sm[bw], bh1 = sm[bw + 4];
                    uint32_t bl0 = sm[bw + (W2L - W2H)], bl1 = sm[bw + (W2L - W2H) + 4];
                    #pragma unroll
                    for (int mt = 0; mt < 2; ++mt) {
                        mma16816(acc[mt][nt], ah[mt], bh0, bh1);
                        mma16816(acc[mt][nt], ah[mt], bl0, bl1);
                        mma16816(acc[mt][nt], al[mt], bh0, bh1);
                    }
                }
            }
            __syncthreads();   // all A reads finished chip^H^Hblock-wide
            #pragma unroll
            for (int mt = 0; mt < 2; ++mt)
                #pragma unroll
                for (int nt = 0; nt < 8; ++nt) {
                    const int col = n0 + 8 * nt + 2 * t;
                    const int r0 = ACT + (m0 + 16 * mt + g) * 132 + col;
                    *(float2*)&smf[r0]           = make_float2(acc[mt][nt][0], acc[mt][nt][1]);
                    *(float2*)&smf[r0 + 8 * 132] = make_float2(acc[mt][nt][2], acc[mt][nt][3]);
                }
        }
        __syncthreads();
        ln_relu(sm, w, lane, B2o, G2o, BT2o);
        __syncthreads();

        // ---- L3: warp w -> rows 16w..16w+15, n=64, k=128 ----
        {
            float acc[8][4];
            #pragma unroll
            for (int nt = 0; nt < 8; ++nt)
                #pragma unroll
                for (int j = 0; j < 4; ++j) acc[nt][j] = 0.0f;
            #pragma unroll
            for (int ks = 0; ks < 8; ++ks) {
                uint32_t ah[4], al[4];
                const int ar = ACT + (16 * w + g) * 132 + 8 * ks + t;
                ah[0] = sm[ar];            ah[2] = sm[ar + 4];
                ah[1] = sm[ar + 8 * 132];  ah[3] = sm[ar + 8 * 132 + 4];
                al[0] = sm[ar + 64];           al[2] = sm[ar + 68];
                al[1] = sm[ar + 8 * 132 + 64]; al[3] = sm[ar + 8 * 132 + 68];
                #pragma unroll
                for (int nt = 0; nt < 8; ++nt) {
                    const int bw = W3H + (8 * nt + g) * 68 + 8 * ks + t;
                    uint32_t bh0 = sm[bw], bh1 = sm[bw + 4];
                    uint32_t bl0 = sm[bw + (W3L - W3H)], bl1 = sm[bw + (W3L - W3H) + 4];
                    mma16816(acc[nt], ah, bh0, bh1);
                    mma16816(acc[nt], ah, bl0, bl1);
                    mma16816(acc[nt], al, bh0, bh1);
                }
            }
            __syncthreads();   // all warps done reading act before overwrite
            #pragma unroll
            for (int nt = 0; nt < 8; ++nt) {
                const int col = 8 * nt + 2 * t;
                const int r0 = ACT + (16 * w + g) * 132 + col;
                *(float2*)&smf[r0]           = make_float2(acc[nt][0], acc[nt][1]);
                *(float2*)&smf[r0 + 8 * 132] = make_float2(acc[nt][2], acc[nt][3]);
            }
        }
        __syncthreads();

        // ---- output copy: +b3, coalesced float4 ----
        {
            const int row = tid >> 1, half = tid & 1;
            const int grow = rbase + row;
            if (grow < M) {
                const float* src = &smf[ACT + row * 132 + half * 32];
                const float* bb = &smf[B3o + half * 32];
                float4* dst = reinterpret_cast<float4*>(out + (size_t)grow * 64 + half * 32);
                #pragma unroll
                for (int j = 0; j < 8; ++j) {
                    float4 v;
                    v.x = src[4 * j + 0] + bb[4 * j + 0];
                    v.y = src[4 * j + 1] + bb[4 * j + 1];
                    v.z = src[4 * j + 2] + bb[4 * j + 2];
                    v.w = src[4 * j + 3] + bb[4 * j + 3];
                    dst[j] = v;
                }
            }
        }
        __syncthreads();
    }
}

extern "C" void kernel_launch(void* const* d_in, const int* in_sizes, int n_in,
                              void* d_out, int out_size) {
    const float* coords    = (const float*)d_in[0];
    const float* ref_theta = (const float*)d_in[1];
    const float* ref_phi   = (const float*)d_in[2];
    const float* W1  = (const float*)d_in[3];
    const float* b1  = (const float*)d_in[4];
    const float* g1  = (const float*)d_in[5];
    const float* bt1 = (const float*)d_in[6];
    const float* W2  = (const float*)d_in[7];
    const float* b2  = (const float*)d_in[8];
    const float* g2  = (const float*)d_in[9];
    const float* bt2 = (const float*)d_in[10];
    const float* W3  = (const float*)d_in[11];
    const float* b3  = (const float*)d_in[12];
    float* out = (float*)d_out;

    const int M = in_sizes[0] / 2;
    const int ntiles = (M + TILE - 1) / TILE;
    const int blocks = ntiles < NSM ? ntiles : NSM;
    const size_t smem = (size_t)SMEM_WORDS * 4;

    cudaFuncSetAttribute(geo_trunk_mma,
                         cudaFuncAttributeMaxDynamicSharedMemorySize, (int)smem);

    geo_trunk_mma<<<blocks, NTH, smem>>>(
        coords, ref_theta, ref_phi,
        W1, b1, g1, bt1, W2, b2, g2, bt2, W3, b3,
        out, M);
}